// round 10
// baseline (speedup 1.0000x reference)
#include <cuda_runtime.h>
#include <cstdint>

// HQQ grouped GEMM: plain fp16 mma.sync pipeline over pre-scaled weights.
// Wh = fp16(s * q); y = x~ . Wh - sum_g s_g*z_g*T_g (exact fp32 correction).
// E=8, K=1024, OUT=2816, GS=64, N=2048.
#define NE 8
#define KDIM 1024
#define ODIM 2816
#define NTOK 2048
#define GD 16           // KDIM/64 quant groups

#define BM 128
#define BN 128
#define BK 32
#define NKT (KDIM / BK) // 32
#define STAGES 3

static __device__ float    T_buf[NTOK * GD];
static __device__ uint16_t Xh_buf[NTOK * KDIM];                       // 4 MB
static __device__ uint16_t Wh_buf[(size_t)NE * KDIM * ODIM];          // 46 MB

__device__ __forceinline__ float h_round(float f) {
    float r;
    asm("{ .reg .f16 t; cvt.rn.f16.f32 t, %1; cvt.f32.f16 %0, t; }"
        : "=f"(r) : "f"(f));
    return r;
}
__device__ __forceinline__ uint32_t cvt2h(float f0, float f1) {
    uint32_t r;
    asm("cvt.rn.f16x2.f32 %0, %1, %2;" : "=r"(r) : "f"(f1), "f"(f0)); // lo = f0
    return r;
}

// ---------------- pre-pass: X -> fp16 scratch + fused group rowsums ----------------
__global__ void __launch_bounds__(256) xcvt_k(const float* __restrict__ X) {
    const int row = blockIdx.x;
    const int t = threadIdx.x;
    const float4 v = *(const float4*)(X + (size_t)row * KDIM + t * 4);
    uint32_t h0 = cvt2h(v.x, v.y), h1 = cvt2h(v.z, v.w);
    *(uint2*)(Xh_buf + (size_t)row * KDIM + t * 4) = make_uint2(h0, h1);
    float s = h_round(v.x) + h_round(v.y) + h_round(v.z) + h_round(v.w);
    s += __shfl_xor_sync(0xffffffffu, s, 1);
    s += __shfl_xor_sync(0xffffffffu, s, 2);
    s += __shfl_xor_sync(0xffffffffu, s, 4);
    s += __shfl_xor_sync(0xffffffffu, s, 8);
    if ((t & 15) == 0) T_buf[row * GD + (t >> 4)] = s;
}

// ---------------- pre-pass: Wh = fp16(scale * q) ----------------
__global__ void __launch_bounds__(256) wcvt_k(const int* __restrict__ Wq,
                                              const float* __restrict__ Sc,
                                              const int* __restrict__ tpe) {
    const size_t i = ((size_t)blockIdx.x * 256 + threadIdx.x) * 8;
    const int e = (int)(i / ((size_t)KDIM * ODIM));
    if (tpe[e] == 0) return;   // expert has no tokens: its W is never read
    const size_t rem = i % ((size_t)KDIM * ODIM);
    const int k = (int)(rem / ODIM);
    const int o = (int)(rem % ODIM);
    const float* sp = Sc + ((size_t)e * GD + (k >> 6)) * ODIM + o;
    const float4 s0 = *(const float4*)sp;
    const float4 s1 = *(const float4*)(sp + 4);
    const int4 a = *(const int4*)(Wq + i);
    const int4 b = *(const int4*)(Wq + i + 4);
    uint4 oV;
    oV.x = cvt2h(s0.x * (float)a.x, s0.y * (float)a.y);
    oV.y = cvt2h(s0.z * (float)a.z, s0.w * (float)a.w);
    oV.z = cvt2h(s1.x * (float)b.x, s1.y * (float)b.y);
    oV.w = cvt2h(s1.z * (float)b.z, s1.w * (float)b.w);
    *(uint4*)(Wh_buf + i) = oV;
}

// ---------------- kernel: Y = - sum_g (s*z)[g,o] * T[n,g] ----------------
__global__ void __launch_bounds__(256) yinit_k(const int* __restrict__ tpe,
                                               const float* __restrict__ Sc,
                                               const float* __restrict__ Zr,
                                               float* __restrict__ Y) {
    __shared__ float Ts[128 * GD];
    const int tid = threadIdx.x;
    const int n0 = blockIdx.x * 128;
    const int m0 = blockIdx.y * 128;
    *(float4*)&Ts[tid * 8]     = *(const float4*)&T_buf[m0 * GD + tid * 8];
    *(float4*)&Ts[tid * 8 + 4] = *(const float4*)&T_buf[m0 * GD + tid * 8 + 4];
    __syncthreads();
    const int c0 = (tid & 31) * 4;
    const int rb = (tid >> 5) * 16;
    int cum = 0;
    for (int e = 0; e < NE; ++e) {
        const int lo = cum; cum += tpe[e];
        const int sLo = max(lo, m0), sHi = min(cum, m0 + 128);
        if (sLo >= sHi) continue;
        const float* Sp = Sc + (size_t)e * GD * ODIM + n0 + c0;
        const float* Zp = Zr + (size_t)e * GD * ODIM + n0 + c0;
        float y[16][4];
#pragma unroll
        for (int i = 0; i < 16; ++i) y[i][0] = y[i][1] = y[i][2] = y[i][3] = 0.f;
#pragma unroll
        for (int g = 0; g < GD; ++g) {
            const float4 s4 = *(const float4*)(Sp + (size_t)g * ODIM);
            const float4 z4 = *(const float4*)(Zp + (size_t)g * ODIM);
            const float4 u = make_float4(s4.x * z4.x, s4.y * z4.y,
                                         s4.z * z4.z, s4.w * z4.w);
#pragma unroll
            for (int i = 0; i < 16; ++i) {
                const float tv = Ts[(rb + i) * GD + g];
                y[i][0] -= u.x * tv; y[i][1] -= u.y * tv;
                y[i][2] -= u.z * tv; y[i][3] -= u.w * tv;
            }
        }
#pragma unroll
        for (int i = 0; i < 16; ++i) {
            const int r = m0 + rb + i;
            if (r >= sLo && r < sHi)
                *(float4*)(Y + (size_t)r * ODIM + n0 + c0) = *(float4*)y[i];
        }
    }
}

// ---------------- main kernel ----------------
#define LDSM4(r, a) asm volatile( \
    "ldmatrix.sync.aligned.m8n8.x4.shared.b16 {%0,%1,%2,%3}, [%4];" \
    : "=r"((r)[0]), "=r"((r)[1]), "=r"((r)[2]), "=r"((r)[3]) : "r"(a))
#define LDSM4T(r, a) asm volatile( \
    "ldmatrix.sync.aligned.m8n8.x4.trans.shared.b16 {%0,%1,%2,%3}, [%4];" \
    : "=r"((r)[0]), "=r"((r)[1]), "=r"((r)[2]), "=r"((r)[3]) : "r"(a))
#define MMAH(d, a, b0, b1) asm volatile( \
    "mma.sync.aligned.m16n8k16.row.col.f32.f16.f16.f32 " \
    "{%0,%1,%2,%3}, {%4,%5,%6,%7}, {%8,%9}, {%0,%1,%2,%3};" \
    : "+f"((d)[0]), "+f"((d)[1]), "+f"((d)[2]), "+f"((d)[3]) \
    : "r"((a)[0]), "r"((a)[1]), "r"((a)[2]), "r"((a)[3]), "r"(b0), "r"(b1))
#define MMAH_Z(d, a, b0, b1) asm volatile( \
    "mma.sync.aligned.m16n8k16.row.col.f32.f16.f16.f32 " \
    "{%0,%1,%2,%3}, {%4,%5,%6,%7}, {%8,%9}, {%10,%10,%10,%10};" \
    : "=f"((d)[0]), "=f"((d)[1]), "=f"((d)[2]), "=f"((d)[3]) \
    : "r"((a)[0]), "r"((a)[1]), "r"((a)[2]), "r"((a)[3]), "r"(b0), "r"(b1), \
      "f"(0.0f))
#define CPA(dst, src) asm volatile( \
    "cp.async.cg.shared.global [%0], [%1], 16;" :: "r"(dst), "l"(src))
#define CPA_COMMIT() asm volatile("cp.async.commit_group;" ::: "memory")
#define CPA_WAIT1() asm volatile("cp.async.wait_group 1;" ::: "memory")
#define CPA_WAIT0() asm volatile("cp.async.wait_group 0;" ::: "memory")

// smem (chunk = 16B = 8 fp16):
//  X stage: 128 rows x 32 k, pitch 64B (4 chunks),  swizzle c' = c ^ ((row>>1)&3)
//  W stage: 32 rows x 128 n, pitch 256B (16 chunks), swizzle c' = c ^ (row&7)
#define XBYTES (BM * BK * 2)   // 8192
#define WBYTES (BK * BN * 2)   // 8192

__global__ void __launch_bounds__(256, 2)
hqq_main(const int* __restrict__ tpe, float* __restrict__ Y)
{
    __shared__ __align__(16) uint16_t XS[STAGES][BM * BK];
    __shared__ __align__(16) uint16_t WS[STAGES][BK * BN];

    const int tid = threadIdx.x;
    const int lane = tid & 31;
    const int wid = tid >> 5;
    const int wm = (wid & 3) * 32;     // 4 m-warps
    const int wn = (wid >> 2) * 64;    // 2 n-warps, 64 cols each
    const int n0 = blockIdx.x * BN;
    const int m0 = blockIdx.y * BM;

    const uint32_t XtB = (uint32_t)__cvta_generic_to_shared(XS);
    const uint32_t WtB = (uint32_t)__cvta_generic_to_shared(WS);

    // ldmatrix byte offsets (stage-relative)
    uint32_t aoff[2][2], boff[2][4];
#pragma unroll
    for (int mi = 0; mi < 2; ++mi)
#pragma unroll
        for (int s = 0; s < 2; ++s) {
            const int r = wm + mi * 16 + (lane & 15);
            const int c = s * 2 + (lane >> 4);
            aoff[mi][s] = (uint32_t)(r * 64 + ((c ^ ((r >> 1) & 3)) << 4));
        }
#pragma unroll
    for (int s = 0; s < 2; ++s)
#pragma unroll
        for (int nb = 0; nb < 4; ++nb) {
            const int r = s * 16 + (lane & 15);
            const int c = (wn >> 3) + nb * 2 + (lane >> 4);
            boff[s][nb] = (uint32_t)(r * 256 + ((c ^ (r & 7)) << 4));
        }

    // cp.async per-thread maps
    const int xr = tid >> 1;
    const int xc0 = (tid & 1) * 2;
    const uint16_t* xsrc = Xh_buf + (size_t)(m0 + xr) * KDIM + (tid & 1) * 16;
    const uint32_t xd0 = (uint32_t)(xr * 64 + (((xc0 + 0) ^ ((xr >> 1) & 3)) << 4));
    const uint32_t xd1 = (uint32_t)(xr * 64 + (((xc0 + 1) ^ ((xr >> 1) & 3)) << 4));
    // W: 32 rows x 16 chunks; each thread does rows wr0 and wr0+16, chunk wc
    const int wr0 = tid >> 4;          // 0..15
    const int wc = tid & 15;           // 0..15
    const uint32_t wd0 = (uint32_t)(wr0 * 256 + ((wc ^ (wr0 & 7)) << 4));
    const uint32_t wd1 = (uint32_t)((wr0 + 16) * 256 + ((wc ^ ((wr0 + 16) & 7)) << 4));

    int cum = 0;
    for (int e = 0; e < NE; ++e) {
        const int lo = cum;
        cum += tpe[e];
        const int sLo = max(lo, m0), sHi = min(cum, m0 + BM);
        if (sLo >= sHi) continue;

        const uint16_t* wsrc0 = Wh_buf + (size_t)e * KDIM * ODIM +
                                (size_t)wr0 * ODIM + n0 + wc * 8;
        const uint16_t* wsrc1 = wsrc0 + (size_t)16 * ODIM;

        // ---- prologue: issue tiles 0..1 ----
#pragma unroll
        for (int p = 0; p < STAGES - 1; ++p) {
            CPA(XtB + p * XBYTES + xd0, xsrc + p * BK);
            CPA(XtB + p * XBYTES + xd1, xsrc + p * BK + 8);
            CPA(WtB + p * WBYTES + wd0, wsrc0 + (size_t)p * BK * ODIM);
            CPA(WtB + p * WBYTES + wd1, wsrc1 + (size_t)p * BK * ODIM);
            CPA_COMMIT();
        }

        float acc[2][8][4];
        for (int t = 0; t < NKT; ++t) {
            CPA_WAIT1();
            __syncthreads();

            if (t + STAGES - 1 < NKT) {
                const int sl = (t + STAGES - 1) % STAGES;
                const int kb = (t + STAGES - 1) * BK;
                CPA(XtB + sl * XBYTES + xd0, xsrc + kb);
                CPA(XtB + sl * XBYTES + xd1, xsrc + kb + 8);
                CPA(WtB + sl * WBYTES + wd0, wsrc0 + (size_t)kb * ODIM);
                CPA(WtB + sl * WBYTES + wd1, wsrc1 + (size_t)kb * ODIM);
            }
            CPA_COMMIT();

            const uint32_t XtBb = XtB + (t % STAGES) * XBYTES;
            const uint32_t WtBb = WtB + (t % STAGES) * WBYTES;

#pragma unroll
            for (int s = 0; s < 2; ++s) {
                uint32_t Av[2][4], Bv[4][4];
                LDSM4(Av[0], XtBb + aoff[0][s]);
                LDSM4(Av[1], XtBb + aoff[1][s]);
                LDSM4T(Bv[0], WtBb + boff[s][0]);
                LDSM4T(Bv[1], WtBb + boff[s][1]);
                LDSM4T(Bv[2], WtBb + boff[s][2]);
                LDSM4T(Bv[3], WtBb + boff[s][3]);
#pragma unroll
                for (int mi = 0; mi < 2; ++mi)
#pragma unroll
                    for (int nj = 0; nj < 8; ++nj) {
                        const uint32_t b0 = Bv[nj >> 1][(nj & 1) * 2];
                        const uint32_t b1 = Bv[nj >> 1][(nj & 1) * 2 + 1];
                        if (t == 0 && s == 0) {
                            MMAH_Z(acc[mi][nj], Av[mi], b0, b1);
                        } else {
                            MMAH(acc[mi][nj], Av[mi], b0, b1);
                        }
                    }
            }
        }
        CPA_WAIT0();
        __syncthreads();

        // ---- epilogue: Y += acc on this expert's rows ----
        const int rbase = m0 + wm + (lane >> 2);
        const int cbase = n0 + wn + (lane & 3) * 2;
#pragma unroll
        for (int mi = 0; mi < 2; ++mi)
#pragma unroll
            for (int nj = 0; nj < 8; ++nj) {
                const int r0 = rbase + mi * 16;
                const int c = cbase + nj * 8;
                if (r0 >= sLo && r0 < sHi) {
                    float2* p = (float2*)(Y + (size_t)r0 * ODIM + c);
                    float2 v = *p;
                    v.x += acc[mi][nj][0]; v.y += acc[mi][nj][1];
                    *p = v;
                }
                const int r1 = r0 + 8;
                if (r1 >= sLo && r1 < sHi) {
                    float2* p = (float2*)(Y + (size_t)r1 * ODIM + c);
                    float2 v = *p;
                    v.x += acc[mi][nj][2]; v.y += acc[mi][nj][3];
                    *p = v;
                }
            }
        __syncthreads();
    }
}

extern "C" void kernel_launch(void* const* d_in, const int* in_sizes, int n_in,
                              void* d_out, int out_size) {
    const float* X   = (const float*)d_in[0];
    const int*   tpe = (const int*)d_in[1];
    const int*   Wq  = (const int*)d_in[2];
    const float* Sc  = (const float*)d_in[3];
    const float* Zr  = (const float*)d_in[4];
    float*       Y   = (float*)d_out;

    xcvt_k<<<NTOK, 256>>>(X);
    wcvt_k<<<(NE * KDIM * ODIM) / (256 * 8), 256>>>(Wq, Sc, tpe);
    dim3 gB(ODIM / 128, NTOK / 128);
    yinit_k<<<gB, 256>>>(tpe, Sc, Zr, Y);
    dim3 gM(ODIM / BN, NTOK / BM);                         // 22 x 16
    hqq_main<<<gM, 256>>>(tpe, Y);
}

// round 11
// speedup vs baseline: 1.0169x; 1.0169x over previous
#include <cuda_runtime.h>
#include <cstdint>

// HQQ grouped GEMM: plain fp16 mma.sync pipeline over pre-scaled weights.
// Wh = fp16(s * q); y = x~ . Wh - sum_g s_g*z_g*T_g (exact fp32 correction).
// R11: BN=128 / 32x64 warp tile (best LSU/MMA ratio) + 4-stage pipeline via
// DYNAMIC smem (64 KB/CTA, beyond the 48 KB static limit), wait_group 2.
// E=8, K=1024, OUT=2816, GS=64, N=2048.
#define NE 8
#define KDIM 1024
#define ODIM 2816
#define NTOK 2048
#define GD 16           // KDIM/64 quant groups

#define BM 128
#define BN 128
#define BK 32
#define NKT (KDIM / BK) // 32
#define STAGES 4

static __device__ float    T_buf[NTOK * GD];
static __device__ uint16_t Xh_buf[NTOK * KDIM];                       // 4 MB
static __device__ uint16_t Wh_buf[(size_t)NE * KDIM * ODIM];          // 46 MB

__device__ __forceinline__ float h_round(float f) {
    float r;
    asm("{ .reg .f16 t; cvt.rn.f16.f32 t, %1; cvt.f32.f16 %0, t; }"
        : "=f"(r) : "f"(f));
    return r;
}
__device__ __forceinline__ uint32_t cvt2h(float f0, float f1) {
    uint32_t r;
    asm("cvt.rn.f16x2.f32 %0, %1, %2;" : "=r"(r) : "f"(f1), "f"(f0)); // lo = f0
    return r;
}

// ---------------- pre-pass: X -> fp16 scratch + fused group rowsums ----------------
__global__ void __launch_bounds__(256) xcvt_k(const float* __restrict__ X) {
    const int row = blockIdx.x;
    const int t = threadIdx.x;
    const float4 v = *(const float4*)(X + (size_t)row * KDIM + t * 4);
    uint32_t h0 = cvt2h(v.x, v.y), h1 = cvt2h(v.z, v.w);
    *(uint2*)(Xh_buf + (size_t)row * KDIM + t * 4) = make_uint2(h0, h1);
    float s = h_round(v.x) + h_round(v.y) + h_round(v.z) + h_round(v.w);
    s += __shfl_xor_sync(0xffffffffu, s, 1);
    s += __shfl_xor_sync(0xffffffffu, s, 2);
    s += __shfl_xor_sync(0xffffffffu, s, 4);
    s += __shfl_xor_sync(0xffffffffu, s, 8);
    if ((t & 15) == 0) T_buf[row * GD + (t >> 4)] = s;
}

// ---------------- pre-pass: Wh = fp16(scale * q) ----------------
__global__ void __launch_bounds__(256) wcvt_k(const int* __restrict__ Wq,
                                              const float* __restrict__ Sc,
                                              const int* __restrict__ tpe) {
    const size_t i = ((size_t)blockIdx.x * 256 + threadIdx.x) * 8;
    const int e = (int)(i / ((size_t)KDIM * ODIM));
    if (tpe[e] == 0) return;   // expert has no tokens: its W is never read
    const size_t rem = i % ((size_t)KDIM * ODIM);
    const int k = (int)(rem / ODIM);
    const int o = (int)(rem % ODIM);
    const float* sp = Sc + ((size_t)e * GD + (k >> 6)) * ODIM + o;
    const float4 s0 = *(const float4*)sp;
    const float4 s1 = *(const float4*)(sp + 4);
    const int4 a = *(const int4*)(Wq + i);
    const int4 b = *(const int4*)(Wq + i + 4);
    uint4 oV;
    oV.x = cvt2h(s0.x * (float)a.x, s0.y * (float)a.y);
    oV.y = cvt2h(s0.z * (float)a.z, s0.w * (float)a.w);
    oV.z = cvt2h(s1.x * (float)b.x, s1.y * (float)b.y);
    oV.w = cvt2h(s1.z * (float)b.z, s1.w * (float)b.w);
    *(uint4*)(Wh_buf + i) = oV;
}

// ---------------- kernel: Y = - sum_g (s*z)[g,o] * T[n,g] ----------------
__global__ void __launch_bounds__(256) yinit_k(const int* __restrict__ tpe,
                                               const float* __restrict__ Sc,
                                               const float* __restrict__ Zr,
                                               float* __restrict__ Y) {
    __shared__ float Ts[128 * GD];
    const int tid = threadIdx.x;
    const int n0 = blockIdx.x * 128;
    const int m0 = blockIdx.y * 128;
    *(float4*)&Ts[tid * 8]     = *(const float4*)&T_buf[m0 * GD + tid * 8];
    *(float4*)&Ts[tid * 8 + 4] = *(const float4*)&T_buf[m0 * GD + tid * 8 + 4];
    __syncthreads();
    const int c0 = (tid & 31) * 4;
    const int rb = (tid >> 5) * 16;
    int cum = 0;
    for (int e = 0; e < NE; ++e) {
        const int lo = cum; cum += tpe[e];
        const int sLo = max(lo, m0), sHi = min(cum, m0 + 128);
        if (sLo >= sHi) continue;
        const float* Sp = Sc + (size_t)e * GD * ODIM + n0 + c0;
        const float* Zp = Zr + (size_t)e * GD * ODIM + n0 + c0;
        float y[16][4];
#pragma unroll
        for (int i = 0; i < 16; ++i) y[i][0] = y[i][1] = y[i][2] = y[i][3] = 0.f;
#pragma unroll
        for (int g = 0; g < GD; ++g) {
            const float4 s4 = *(const float4*)(Sp + (size_t)g * ODIM);
            const float4 z4 = *(const float4*)(Zp + (size_t)g * ODIM);
            const float4 u = make_float4(s4.x * z4.x, s4.y * z4.y,
                                         s4.z * z4.z, s4.w * z4.w);
#pragma unroll
            for (int i = 0; i < 16; ++i) {
                const float tv = Ts[(rb + i) * GD + g];
                y[i][0] -= u.x * tv; y[i][1] -= u.y * tv;
                y[i][2] -= u.z * tv; y[i][3] -= u.w * tv;
            }
        }
#pragma unroll
        for (int i = 0; i < 16; ++i) {
            const int r = m0 + rb + i;
            if (r >= sLo && r < sHi)
                *(float4*)(Y + (size_t)r * ODIM + n0 + c0) = *(float4*)y[i];
        }
    }
}

// ---------------- main kernel ----------------
#define LDSM4(r, a) asm volatile( \
    "ldmatrix.sync.aligned.m8n8.x4.shared.b16 {%0,%1,%2,%3}, [%4];" \
    : "=r"((r)[0]), "=r"((r)[1]), "=r"((r)[2]), "=r"((r)[3]) : "r"(a))
#define LDSM4T(r, a) asm volatile( \
    "ldmatrix.sync.aligned.m8n8.x4.trans.shared.b16 {%0,%1,%2,%3}, [%4];" \
    : "=r"((r)[0]), "=r"((r)[1]), "=r"((r)[2]), "=r"((r)[3]) : "r"(a))
#define MMAH(d, a, b0, b1) asm volatile( \
    "mma.sync.aligned.m16n8k16.row.col.f32.f16.f16.f32 " \
    "{%0,%1,%2,%3}, {%4,%5,%6,%7}, {%8,%9}, {%0,%1,%2,%3};" \
    : "+f"((d)[0]), "+f"((d)[1]), "+f"((d)[2]), "+f"((d)[3]) \
    : "r"((a)[0]), "r"((a)[1]), "r"((a)[2]), "r"((a)[3]), "r"(b0), "r"(b1))
#define MMAH_Z(d, a, b0, b1) asm volatile( \
    "mma.sync.aligned.m16n8k16.row.col.f32.f16.f16.f32 " \
    "{%0,%1,%2,%3}, {%4,%5,%6,%7}, {%8,%9}, {%10,%10,%10,%10};" \
    : "=f"((d)[0]), "=f"((d)[1]), "=f"((d)[2]), "=f"((d)[3]) \
    : "r"((a)[0]), "r"((a)[1]), "r"((a)[2]), "r"((a)[3]), "r"(b0), "r"(b1), \
      "f"(0.0f))
#define CPA(dst, src) asm volatile( \
    "cp.async.cg.shared.global [%0], [%1], 16;" :: "r"(dst), "l"(src))
#define CPA_COMMIT() asm volatile("cp.async.commit_group;" ::: "memory")
#define CPA_WAIT2() asm volatile("cp.async.wait_group 2;" ::: "memory")
#define CPA_WAIT0() asm volatile("cp.async.wait_group 0;" ::: "memory")

// smem (chunk = 16B = 8 fp16):
//  X stage: 128 rows x 32 k, pitch 64B (4 chunks),   swizzle c' = c ^ ((row>>1)&3)
//  W stage: 32 rows x 128 n, pitch 256B (16 chunks), swizzle c' = c ^ (row&7)
#define XBYTES (BM * BK * 2)   // 8192
#define WBYTES (BK * BN * 2)   // 8192
#define SMEM_TOTAL (STAGES * (XBYTES + WBYTES))  // 65536

__global__ void __launch_bounds__(256, 2)
hqq_main(const int* __restrict__ tpe, float* __restrict__ Y)
{
    extern __shared__ __align__(16) uint16_t smem[];

    const int tid = threadIdx.x;
    const int lane = tid & 31;
    const int wid = tid >> 5;
    const int wm = (wid & 3) * 32;     // 4 m-warps
    const int wn = (wid >> 2) * 64;    // 2 n-warps, 64 cols each
    const int n0 = blockIdx.x * BN;
    const int m0 = blockIdx.y * BM;

    const uint32_t XtB = (uint32_t)__cvta_generic_to_shared(smem);
    const uint32_t WtB = XtB + STAGES * XBYTES;

    // ldmatrix byte offsets (stage-relative)
    uint32_t aoff[2][2], boff[2][4];
#pragma unroll
    for (int mi = 0; mi < 2; ++mi)
#pragma unroll
        for (int s = 0; s < 2; ++s) {
            const int r = wm + mi * 16 + (lane & 15);
            const int c = s * 2 + (lane >> 4);
            aoff[mi][s] = (uint32_t)(r * 64 + ((c ^ ((r >> 1) & 3)) << 4));
        }
#pragma unroll
    for (int s = 0; s < 2; ++s)
#pragma unroll
        for (int nb = 0; nb < 4; ++nb) {
            const int r = s * 16 + (lane & 15);
            const int c = (wn >> 3) + nb * 2 + (lane >> 4);
            boff[s][nb] = (uint32_t)(r * 256 + ((c ^ (r & 7)) << 4));
        }

    // cp.async per-thread maps
    const int xr = tid >> 1;
    const int xc0 = (tid & 1) * 2;
    const uint16_t* xsrc = Xh_buf + (size_t)(m0 + xr) * KDIM + (tid & 1) * 16;
    const uint32_t xd0 = (uint32_t)(xr * 64 + (((xc0 + 0) ^ ((xr >> 1) & 3)) << 4));
    const uint32_t xd1 = (uint32_t)(xr * 64 + (((xc0 + 1) ^ ((xr >> 1) & 3)) << 4));
    // W: 32 rows x 16 chunks; each thread does rows wr0 and wr0+16, chunk wc
    const int wr0 = tid >> 4;          // 0..15
    const int wc = tid & 15;           // 0..15
    const uint32_t wd0 = (uint32_t)(wr0 * 256 + ((wc ^ (wr0 & 7)) << 4));
    const uint32_t wd1 = (uint32_t)((wr0 + 16) * 256 + ((wc ^ ((wr0 + 16) & 7)) << 4));

    int cum = 0;
    for (int e = 0; e < NE; ++e) {
        const int lo = cum;
        cum += tpe[e];
        const int sLo = max(lo, m0), sHi = min(cum, m0 + BM);
        if (sLo >= sHi) continue;

        const uint16_t* wsrc0 = Wh_buf + (size_t)e * KDIM * ODIM +
                                (size_t)wr0 * ODIM + n0 + wc * 8;
        const uint16_t* wsrc1 = wsrc0 + (size_t)16 * ODIM;

        // ---- prologue: issue tiles 0..2 ----
#pragma unroll
        for (int p = 0; p < STAGES - 1; ++p) {
            CPA(XtB + p * XBYTES + xd0, xsrc + p * BK);
            CPA(XtB + p * XBYTES + xd1, xsrc + p * BK + 8);
            CPA(WtB + p * WBYTES + wd0, wsrc0 + (size_t)p * BK * ODIM);
            CPA(WtB + p * WBYTES + wd1, wsrc1 + (size_t)p * BK * ODIM);
            CPA_COMMIT();
        }

        float acc[2][8][4];
        for (int t = 0; t < NKT; ++t) {
            CPA_WAIT2();
            __syncthreads();

            if (t + STAGES - 1 < NKT) {
                const int sl = (t + STAGES - 1) & (STAGES - 1);
                const int kb = (t + STAGES - 1) * BK;
                CPA(XtB + sl * XBYTES + xd0, xsrc + kb);
                CPA(XtB + sl * XBYTES + xd1, xsrc + kb + 8);
                CPA(WtB + sl * WBYTES + wd0, wsrc0 + (size_t)kb * ODIM);
                CPA(WtB + sl * WBYTES + wd1, wsrc1 + (size_t)kb * ODIM);
            }
            CPA_COMMIT();

            const uint32_t XtBb = XtB + (t & (STAGES - 1)) * XBYTES;
            const uint32_t WtBb = WtB + (t & (STAGES - 1)) * WBYTES;

#pragma unroll
            for (int s = 0; s < 2; ++s) {
                uint32_t Av[2][4], Bv[4][4];
                LDSM4(Av[0], XtBb + aoff[0][s]);
                LDSM4(Av[1], XtBb + aoff[1][s]);
                LDSM4T(Bv[0], WtBb + boff[s][0]);
                LDSM4T(Bv[1], WtBb + boff[s][1]);
                LDSM4T(Bv[2], WtBb + boff[s][2]);
                LDSM4T(Bv[3], WtBb + boff[s][3]);
#pragma unroll
                for (int mi = 0; mi < 2; ++mi)
#pragma unroll
                    for (int nj = 0; nj < 8; ++nj) {
                        const uint32_t b0 = Bv[nj >> 1][(nj & 1) * 2];
                        const uint32_t b1 = Bv[nj >> 1][(nj & 1) * 2 + 1];
                        if (t == 0 && s == 0) {
                            MMAH_Z(acc[mi][nj], Av[mi], b0, b1);
                        } else {
                            MMAH(acc[mi][nj], Av[mi], b0, b1);
                        }
                    }
            }
        }
        CPA_WAIT0();
        __syncthreads();

        // ---- epilogue: Y += acc on this expert's rows ----
        const int rbase = m0 + wm + (lane >> 2);
        const int cbase = n0 + wn + (lane & 3) * 2;
#pragma unroll
        for (int mi = 0; mi < 2; ++mi)
#pragma unroll
            for (int nj = 0; nj < 8; ++nj) {
                const int r0 = rbase + mi * 16;
                const int c = cbase + nj * 8;
                if (r0 >= sLo && r0 < sHi) {
                    float2* p = (float2*)(Y + (size_t)r0 * ODIM + c);
                    float2 v = *p;
                    v.x += acc[mi][nj][0]; v.y += acc[mi][nj][1];
                    *p = v;
                }
                const int r1 = r0 + 8;
                if (r1 >= sLo && r1 < sHi) {
                    float2* p = (float2*)(Y + (size_t)r1 * ODIM + c);
                    float2 v = *p;
                    v.x += acc[mi][nj][2]; v.y += acc[mi][nj][3];
                    *p = v;
                }
            }
        __syncthreads();
    }
}

extern "C" void kernel_launch(void* const* d_in, const int* in_sizes, int n_in,
                              void* d_out, int out_size) {
    const float* X   = (const float*)d_in[0];
    const int*   tpe = (const int*)d_in[1];
    const int*   Wq  = (const int*)d_in[2];
    const float* Sc  = (const float*)d_in[3];
    const float* Zr  = (const float*)d_in[4];
    float*       Y   = (float*)d_out;

    cudaFuncSetAttribute(hqq_main,
                         cudaFuncAttributeMaxDynamicSharedMemorySize, SMEM_TOTAL);

    xcvt_k<<<NTOK, 256>>>(X);
    wcvt_k<<<(NE * KDIM * ODIM) / (256 * 8), 256>>>(Wq, Sc, tpe);
    dim3 gB(ODIM / 128, NTOK / 128);
    yinit_k<<<gB, 256>>>(tpe, Sc, Zr, Y);
    dim3 gM(ODIM / BN, NTOK / BM);                         // 22 x 16
    hqq_main<<<gM, 256, SMEM_TOTAL>>>(tpe, Y);
}

// round 12
// speedup vs baseline: 1.1328x; 1.1139x over previous
#include <cuda_runtime.h>
#include <cstdint>

// HQQ grouped GEMM: plain fp16 mma.sync pipeline over pre-scaled weights.
// Wh = fp16(s * q); y = x~ . Wh - sum_g s_g*z_g*T_g (exact fp32 correction).
// R12 = R9 config (BM128/BN64/BK32, 4-stage cp.async, warp 32x32) with
// __launch_bounds__(256,4): force 64 regs -> 32 warps/SM (occ 50%).
// E=8, K=1024, OUT=2816, GS=64, N=2048.
#define NE 8
#define KDIM 1024
#define ODIM 2816
#define NTOK 2048
#define GD 16           // KDIM/64 quant groups

#define BM 128
#define BN 64
#define BK 32
#define NKT (KDIM / BK) // 32
#define STAGES 4

static __device__ float    T_buf[NTOK * GD];
static __device__ uint16_t Xh_buf[NTOK * KDIM];                       // 4 MB
static __device__ uint16_t Wh_buf[(size_t)NE * KDIM * ODIM];          // 46 MB

__device__ __forceinline__ float h_round(float f) {
    float r;
    asm("{ .reg .f16 t; cvt.rn.f16.f32 t, %1; cvt.f32.f16 %0, t; }"
        : "=f"(r) : "f"(f));
    return r;
}
__device__ __forceinline__ uint32_t cvt2h(float f0, float f1) {
    uint32_t r;
    asm("cvt.rn.f16x2.f32 %0, %1, %2;" : "=r"(r) : "f"(f1), "f"(f0)); // lo = f0
    return r;
}

// ---------------- pre-pass: X -> fp16 scratch + fused group rowsums ----------------
__global__ void __launch_bounds__(256) xcvt_k(const float* __restrict__ X) {
    const int row = blockIdx.x;
    const int t = threadIdx.x;
    const float4 v = *(const float4*)(X + (size_t)row * KDIM + t * 4);
    uint32_t h0 = cvt2h(v.x, v.y), h1 = cvt2h(v.z, v.w);
    *(uint2*)(Xh_buf + (size_t)row * KDIM + t * 4) = make_uint2(h0, h1);
    float s = h_round(v.x) + h_round(v.y) + h_round(v.z) + h_round(v.w);
    s += __shfl_xor_sync(0xffffffffu, s, 1);
    s += __shfl_xor_sync(0xffffffffu, s, 2);
    s += __shfl_xor_sync(0xffffffffu, s, 4);
    s += __shfl_xor_sync(0xffffffffu, s, 8);
    if ((t & 15) == 0) T_buf[row * GD + (t >> 4)] = s;
}

// ---------------- pre-pass: Wh = fp16(scale * q) ----------------
__global__ void __launch_bounds__(256) wcvt_k(const int* __restrict__ Wq,
                                              const float* __restrict__ Sc,
                                              const int* __restrict__ tpe) {
    const size_t i = ((size_t)blockIdx.x * 256 + threadIdx.x) * 8;
    const int e = (int)(i / ((size_t)KDIM * ODIM));
    if (tpe[e] == 0) return;   // expert has no tokens: its W is never read
    const size_t rem = i % ((size_t)KDIM * ODIM);
    const int k = (int)(rem / ODIM);
    const int o = (int)(rem % ODIM);
    const float* sp = Sc + ((size_t)e * GD + (k >> 6)) * ODIM + o;
    const float4 s0 = *(const float4*)sp;
    const float4 s1 = *(const float4*)(sp + 4);
    const int4 a = *(const int4*)(Wq + i);
    const int4 b = *(const int4*)(Wq + i + 4);
    uint4 oV;
    oV.x = cvt2h(s0.x * (float)a.x, s0.y * (float)a.y);
    oV.y = cvt2h(s0.z * (float)a.z, s0.w * (float)a.w);
    oV.z = cvt2h(s1.x * (float)b.x, s1.y * (float)b.y);
    oV.w = cvt2h(s1.z * (float)b.z, s1.w * (float)b.w);
    *(uint4*)(Wh_buf + i) = oV;
}

// ---------------- kernel: Y = - sum_g (s*z)[g,o] * T[n,g] ----------------
__global__ void __launch_bounds__(256) yinit_k(const int* __restrict__ tpe,
                                               const float* __restrict__ Sc,
                                               const float* __restrict__ Zr,
                                               float* __restrict__ Y) {
    __shared__ float Ts[128 * GD];
    const int tid = threadIdx.x;
    const int n0 = blockIdx.x * 128;
    const int m0 = blockIdx.y * 128;
    *(float4*)&Ts[tid * 8]     = *(const float4*)&T_buf[m0 * GD + tid * 8];
    *(float4*)&Ts[tid * 8 + 4] = *(const float4*)&T_buf[m0 * GD + tid * 8 + 4];
    __syncthreads();
    const int c0 = (tid & 31) * 4;
    const int rb = (tid >> 5) * 16;
    int cum = 0;
    for (int e = 0; e < NE; ++e) {
        const int lo = cum; cum += tpe[e];
        const int sLo = max(lo, m0), sHi = min(cum, m0 + 128);
        if (sLo >= sHi) continue;
        const float* Sp = Sc + (size_t)e * GD * ODIM + n0 + c0;
        const float* Zp = Zr + (size_t)e * GD * ODIM + n0 + c0;
        float y[16][4];
#pragma unroll
        for (int i = 0; i < 16; ++i) y[i][0] = y[i][1] = y[i][2] = y[i][3] = 0.f;
#pragma unroll
        for (int g = 0; g < GD; ++g) {
            const float4 s4 = *(const float4*)(Sp + (size_t)g * ODIM);
            const float4 z4 = *(const float4*)(Zp + (size_t)g * ODIM);
            const float4 u = make_float4(s4.x * z4.x, s4.y * z4.y,
                                         s4.z * z4.z, s4.w * z4.w);
#pragma unroll
            for (int i = 0; i < 16; ++i) {
                const float tv = Ts[(rb + i) * GD + g];
                y[i][0] -= u.x * tv; y[i][1] -= u.y * tv;
                y[i][2] -= u.z * tv; y[i][3] -= u.w * tv;
            }
        }
#pragma unroll
        for (int i = 0; i < 16; ++i) {
            const int r = m0 + rb + i;
            if (r >= sLo && r < sHi)
                *(float4*)(Y + (size_t)r * ODIM + n0 + c0) = *(float4*)y[i];
        }
    }
}

// ---------------- main kernel ----------------
#define LDSM4(r, a) asm volatile( \
    "ldmatrix.sync.aligned.m8n8.x4.shared.b16 {%0,%1,%2,%3}, [%4];" \
    : "=r"((r)[0]), "=r"((r)[1]), "=r"((r)[2]), "=r"((r)[3]) : "r"(a))
#define LDSM4T(r, a) asm volatile( \
    "ldmatrix.sync.aligned.m8n8.x4.trans.shared.b16 {%0,%1,%2,%3}, [%4];" \
    : "=r"((r)[0]), "=r"((r)[1]), "=r"((r)[2]), "=r"((r)[3]) : "r"(a))
#define MMAH(d, a, b0, b1) asm volatile( \
    "mma.sync.aligned.m16n8k16.row.col.f32.f16.f16.f32 " \
    "{%0,%1,%2,%3}, {%4,%5,%6,%7}, {%8,%9}, {%0,%1,%2,%3};" \
    : "+f"((d)[0]), "+f"((d)[1]), "+f"((d)[2]), "+f"((d)[3]) \
    : "r"((a)[0]), "r"((a)[1]), "r"((a)[2]), "r"((a)[3]), "r"(b0), "r"(b1))
#define MMAH_Z(d, a, b0, b1) asm volatile( \
    "mma.sync.aligned.m16n8k16.row.col.f32.f16.f16.f32 " \
    "{%0,%1,%2,%3}, {%4,%5,%6,%7}, {%8,%9}, {%10,%10,%10,%10};" \
    : "=f"((d)[0]), "=f"((d)[1]), "=f"((d)[2]), "=f"((d)[3]) \
    : "r"((a)[0]), "r"((a)[1]), "r"((a)[2]), "r"((a)[3]), "r"(b0), "r"(b1), \
      "f"(0.0f))
#define CPA(dst, src) asm volatile( \
    "cp.async.cg.shared.global [%0], [%1], 16;" :: "r"(dst), "l"(src))
#define CPA_COMMIT() asm volatile("cp.async.commit_group;" ::: "memory")
#define CPA_WAIT2() asm volatile("cp.async.wait_group 2;" ::: "memory")
#define CPA_WAIT0() asm volatile("cp.async.wait_group 0;" ::: "memory")

#define XBYTES (BM * BK * 2)   // 8192
#define WBYTES (BK * BN * 2)   // 4096

__global__ void __launch_bounds__(256, 4)
hqq_main(const int* __restrict__ tpe, float* __restrict__ Y)
{
    __shared__ __align__(16) uint16_t XS[STAGES][BM * BK];
    __shared__ __align__(16) uint16_t WS[STAGES][BK * BN];

    const int tid = threadIdx.x;
    const int lane = tid & 31;
    const int wid = tid >> 5;
    const int wm = (wid & 3) * 32;
    const int wn = (wid >> 2) * 32;
    const int n0 = blockIdx.x * BN;
    const int m0 = blockIdx.y * BM;

    const uint32_t XtB = (uint32_t)__cvta_generic_to_shared(XS);
    const uint32_t WtB = (uint32_t)__cvta_generic_to_shared(WS);

    uint32_t aoff[2][2], boff[2][2];
#pragma unroll
    for (int mi = 0; mi < 2; ++mi)
#pragma unroll
        for (int s = 0; s < 2; ++s) {
            const int r = wm + mi * 16 + (lane & 15);
            const int c = s * 2 + (lane >> 4);
            aoff[mi][s] = (uint32_t)(r * 64 + ((c ^ ((r >> 1) & 3)) << 4));
        }
#pragma unroll
    for (int s = 0; s < 2; ++s)
#pragma unroll
        for (int nb = 0; nb < 2; ++nb) {
            const int r = s * 16 + (lane & 15);
            const int c = (wn >> 3) + nb * 2 + (lane >> 4);
            boff[s][nb] = (uint32_t)(r * 128 + ((c ^ (r & 7)) << 4));
        }

    // cp.async per-thread maps
    const int xr = tid >> 1;
    const int xc0 = (tid & 1) * 2;
    const uint16_t* xsrc = Xh_buf + (size_t)(m0 + xr) * KDIM + (tid & 1) * 16;
    const uint32_t xd0 = (uint32_t)(xr * 64 + (((xc0 + 0) ^ ((xr >> 1) & 3)) << 4));
    const uint32_t xd1 = (uint32_t)(xr * 64 + (((xc0 + 1) ^ ((xr >> 1) & 3)) << 4));
    const int wr = tid >> 3;
    const int wc = tid & 7;
    const uint32_t wd = (uint32_t)(wr * 128 + ((wc ^ (wr & 7)) << 4));

    int cum = 0;
    for (int e = 0; e < NE; ++e) {
        const int lo = cum;
        cum += tpe[e];
        const int sLo = max(lo, m0), sHi = min(cum, m0 + BM);
        if (sLo >= sHi) continue;

        const uint16_t* wsrc = Wh_buf + (size_t)e * KDIM * ODIM +
                               (size_t)wr * ODIM + n0 + wc * 8;

        // ---- prologue: issue tiles 0..2 ----
#pragma unroll
        for (int p = 0; p < STAGES - 1; ++p) {
            CPA(XtB + p * XBYTES + xd0, xsrc + p * BK);
            CPA(XtB + p * XBYTES + xd1, xsrc + p * BK + 8);
            CPA(WtB + p * WBYTES + wd, wsrc + (size_t)p * BK * ODIM);
            CPA_COMMIT();
        }

        float acc[2][4][4];
        for (int t = 0; t < NKT; ++t) {
            CPA_WAIT2();
            __syncthreads();

            if (t + STAGES - 1 < NKT) {
                const int sl = (t + STAGES - 1) & (STAGES - 1);
                const int kb = (t + STAGES - 1) * BK;
                CPA(XtB + sl * XBYTES + xd0, xsrc + kb);
                CPA(XtB + sl * XBYTES + xd1, xsrc + kb + 8);
                CPA(WtB + sl * WBYTES + wd, wsrc + (size_t)kb * ODIM);
            }
            CPA_COMMIT();

            const uint32_t XtBb = XtB + (t & (STAGES - 1)) * XBYTES;
            const uint32_t WtBb = WtB + (t & (STAGES - 1)) * WBYTES;

#pragma unroll
            for (int s = 0; s < 2; ++s) {
                uint32_t Av[2][4], Bv[2][4];
                LDSM4(Av[0], XtBb + aoff[0][s]);
                LDSM4(Av[1], XtBb + aoff[1][s]);
                LDSM4T(Bv[0], WtBb + boff[s][0]);
                LDSM4T(Bv[1], WtBb + boff[s][1]);
#pragma unroll
                for (int mi = 0; mi < 2; ++mi)
#pragma unroll
                    for (int nj = 0; nj < 4; ++nj) {
                        const uint32_t b0 = Bv[nj >> 1][(nj & 1) * 2];
                        const uint32_t b1 = Bv[nj >> 1][(nj & 1) * 2 + 1];
                        if (t == 0 && s == 0) {
                            MMAH_Z(acc[mi][nj], Av[mi], b0, b1);
                        } else {
                            MMAH(acc[mi][nj], Av[mi], b0, b1);
                        }
                    }
            }
        }
        CPA_WAIT0();
        __syncthreads();

        // ---- epilogue: Y += acc on this expert's rows ----
        const int rbase = m0 + wm + (lane >> 2);
        const int cbase = n0 + wn + (lane & 3) * 2;
#pragma unroll
        for (int mi = 0; mi < 2; ++mi)
#pragma unroll
            for (int nj = 0; nj < 4; ++nj) {
                const int r0 = rbase + mi * 16;
                const int c = cbase + nj * 8;
                if (r0 >= sLo && r0 < sHi) {
                    float2* p = (float2*)(Y + (size_t)r0 * ODIM + c);
                    float2 v = *p;
                    v.x += acc[mi][nj][0]; v.y += acc[mi][nj][1];
                    *p = v;
                }
                const int r1 = r0 + 8;
                if (r1 >= sLo && r1 < sHi) {
                    float2* p = (float2*)(Y + (size_t)r1 * ODIM + c);
                    float2 v = *p;
                    v.x += acc[mi][nj][2]; v.y += acc[mi][nj][3];
                    *p = v;
                }
            }
        __syncthreads();
    }
}

extern "C" void kernel_launch(void* const* d_in, const int* in_sizes, int n_in,
                              void* d_out, int out_size) {
    const float* X   = (const float*)d_in[0];
    const int*   tpe = (const int*)d_in[1];
    const int*   Wq  = (const int*)d_in[2];
    const float* Sc  = (const float*)d_in[3];
    const float* Zr  = (const float*)d_in[4];
    float*       Y   = (float*)d_out;

    xcvt_k<<<NTOK, 256>>>(X);
    wcvt_k<<<(NE * KDIM * ODIM) / (256 * 8), 256>>>(Wq, Sc, tpe);
    dim3 gB(ODIM / 128, NTOK / 128);
    yinit_k<<<gB, 256>>>(tpe, Sc, Zr, Y);
    dim3 gM(ODIM / BN, NTOK / BM);                         // 44 x 16
    hqq_main<<<gM, 256>>>(tpe, Y);
}

// round 13
// speedup vs baseline: 1.2192x; 1.0762x over previous
#include <cuda_runtime.h>
#include <cstdint>

// HQQ grouped GEMM: plain fp16 mma.sync pipeline over pre-scaled weights.
// Wh = fp16(s * q); y = x~ . Wh - sum_g s_g*z_g*T_g (exact fp32 correction).
// R13 = R9 config (BM128/BN64/BK32, 4-stage cp.async, 3 CTAs/SM) with
// branch-free accumulators, unroll-4 mainloop, and higher-ILP wcvt.
// E=8, K=1024, OUT=2816, GS=64, N=2048.
#define NE 8
#define KDIM 1024
#define ODIM 2816
#define NTOK 2048
#define GD 16           // KDIM/64 quant groups

#define BM 128
#define BN 64
#define BK 32
#define NKT (KDIM / BK) // 32
#define STAGES 4

static __device__ float    T_buf[NTOK * GD];
static __device__ uint16_t Xh_buf[NTOK * KDIM];                       // 4 MB
static __device__ uint16_t Wh_buf[(size_t)NE * KDIM * ODIM];          // 46 MB

__device__ __forceinline__ float h_round(float f) {
    float r;
    asm("{ .reg .f16 t; cvt.rn.f16.f32 t, %1; cvt.f32.f16 %0, t; }"
        : "=f"(r) : "f"(f));
    return r;
}
__device__ __forceinline__ uint32_t cvt2h(float f0, float f1) {
    uint32_t r;
    asm("cvt.rn.f16x2.f32 %0, %1, %2;" : "=r"(r) : "f"(f1), "f"(f0)); // lo = f0
    return r;
}

// ---------------- pre-pass: X -> fp16 scratch + fused group rowsums ----------------
__global__ void __launch_bounds__(256) xcvt_k(const float* __restrict__ X) {
    const int row = blockIdx.x;
    const int t = threadIdx.x;
    const float4 v = *(const float4*)(X + (size_t)row * KDIM + t * 4);
    uint32_t h0 = cvt2h(v.x, v.y), h1 = cvt2h(v.z, v.w);
    *(uint2*)(Xh_buf + (size_t)row * KDIM + t * 4) = make_uint2(h0, h1);
    float s = h_round(v.x) + h_round(v.y) + h_round(v.z) + h_round(v.w);
    s += __shfl_xor_sync(0xffffffffu, s, 1);
    s += __shfl_xor_sync(0xffffffffu, s, 2);
    s += __shfl_xor_sync(0xffffffffu, s, 4);
    s += __shfl_xor_sync(0xffffffffu, s, 8);
    if ((t & 15) == 0) T_buf[row * GD + (t >> 4)] = s;
}

// ---------------- pre-pass: Wh = fp16(scale * q), 16 elems/thread ----------------
__global__ void __launch_bounds__(256) wcvt_k(const int* __restrict__ Wq,
                                              const float* __restrict__ Sc,
                                              const int* __restrict__ tpe) {
    const size_t i = ((size_t)blockIdx.x * 256 + threadIdx.x) * 16;
    const int e = (int)(i / ((size_t)KDIM * ODIM));
    if (tpe[e] == 0) return;   // expert has no tokens: its W is never read
    const size_t rem = i % ((size_t)KDIM * ODIM);
    const int k = (int)(rem / ODIM);
    const int o = (int)(rem % ODIM);
    const float* sp = Sc + ((size_t)e * GD + (k >> 6)) * ODIM + o;
    // 16 contiguous elems: same k row, same quant group (16 | ODIM, ODIM%64 spans ok
    // since group index depends only on k). 4 independent W loads + 4 scale loads.
    int4 a0 = *(const int4*)(Wq + i);
    int4 a1 = *(const int4*)(Wq + i + 4);
    int4 a2 = *(const int4*)(Wq + i + 8);
    int4 a3 = *(const int4*)(Wq + i + 12);
    float4 s0 = *(const float4*)sp;
    float4 s1 = *(const float4*)(sp + 4);
    float4 s2 = *(const float4*)(sp + 8);
    float4 s3 = *(const float4*)(sp + 12);
    uint4 o0, o1;
    o0.x = cvt2h(s0.x * (float)a0.x, s0.y * (float)a0.y);
    o0.y = cvt2h(s0.z * (float)a0.z, s0.w * (float)a0.w);
    o0.z = cvt2h(s1.x * (float)a1.x, s1.y * (float)a1.y);
    o0.w = cvt2h(s1.z * (float)a1.z, s1.w * (float)a1.w);
    o1.x = cvt2h(s2.x * (float)a2.x, s2.y * (float)a2.y);
    o1.y = cvt2h(s2.z * (float)a2.z, s2.w * (float)a2.w);
    o1.z = cvt2h(s3.x * (float)a3.x, s3.y * (float)a3.y);
    o1.w = cvt2h(s3.z * (float)a3.z, s3.w * (float)a3.w);
    *(uint4*)(Wh_buf + i) = o0;
    *(uint4*)(Wh_buf + i + 8) = o1;
}

// ---------------- kernel: Y = - sum_g (s*z)[g,o] * T[n,g] ----------------
__global__ void __launch_bounds__(256) yinit_k(const int* __restrict__ tpe,
                                               const float* __restrict__ Sc,
                                               const float* __restrict__ Zr,
                                               float* __restrict__ Y) {
    __shared__ float Ts[128 * GD];
    const int tid = threadIdx.x;
    const int n0 = blockIdx.x * 128;
    const int m0 = blockIdx.y * 128;
    *(float4*)&Ts[tid * 8]     = *(const float4*)&T_buf[m0 * GD + tid * 8];
    *(float4*)&Ts[tid * 8 + 4] = *(const float4*)&T_buf[m0 * GD + tid * 8 + 4];
    __syncthreads();
    const int c0 = (tid & 31) * 4;
    const int rb = (tid >> 5) * 16;
    int cum = 0;
    for (int e = 0; e < NE; ++e) {
        const int lo = cum; cum += tpe[e];
        const int sLo = max(lo, m0), sHi = min(cum, m0 + 128);
        if (sLo >= sHi) continue;
        const float* Sp = Sc + (size_t)e * GD * ODIM + n0 + c0;
        const float* Zp = Zr + (size_t)e * GD * ODIM + n0 + c0;
        float y[16][4];
#pragma unroll
        for (int i = 0; i < 16; ++i) y[i][0] = y[i][1] = y[i][2] = y[i][3] = 0.f;
#pragma unroll
        for (int g = 0; g < GD; ++g) {
            const float4 s4 = *(const float4*)(Sp + (size_t)g * ODIM);
            const float4 z4 = *(const float4*)(Zp + (size_t)g * ODIM);
            const float4 u = make_float4(s4.x * z4.x, s4.y * z4.y,
                                         s4.z * z4.z, s4.w * z4.w);
#pragma unroll
            for (int i = 0; i < 16; ++i) {
                const float tv = Ts[(rb + i) * GD + g];
                y[i][0] -= u.x * tv; y[i][1] -= u.y * tv;
                y[i][2] -= u.z * tv; y[i][3] -= u.w * tv;
            }
        }
#pragma unroll
        for (int i = 0; i < 16; ++i) {
            const int r = m0 + rb + i;
            if (r >= sLo && r < sHi)
                *(float4*)(Y + (size_t)r * ODIM + n0 + c0) = *(float4*)y[i];
        }
    }
}

// ---------------- main kernel ----------------
#define LDSM4(r, a) asm volatile( \
    "ldmatrix.sync.aligned.m8n8.x4.shared.b16 {%0,%1,%2,%3}, [%4];" \
    : "=r"((r)[0]), "=r"((r)[1]), "=r"((r)[2]), "=r"((r)[3]) : "r"(a))
#define LDSM4T(r, a) asm volatile( \
    "ldmatrix.sync.aligned.m8n8.x4.trans.shared.b16 {%0,%1,%2,%3}, [%4];" \
    : "=r"((r)[0]), "=r"((r)[1]), "=r"((r)[2]), "=r"((r)[3]) : "r"(a))
#define MMAH(d, a, b0, b1) asm volatile( \
    "mma.sync.aligned.m16n8k16.row.col.f32.f16.f16.f32 " \
    "{%0,%1,%2,%3}, {%4,%5,%6,%7}, {%8,%9}, {%0,%1,%2,%3};" \
    : "+f"((d)[0]), "+f"((d)[1]), "+f"((d)[2]), "+f"((d)[3]) \
    : "r"((a)[0]), "r"((a)[1]), "r"((a)[2]), "r"((a)[3]), "r"(b0), "r"(b1))
#define CPA(dst, src) asm volatile( \
    "cp.async.cg.shared.global [%0], [%1], 16;" :: "r"(dst), "l"(src))
#define CPA_COMMIT() asm volatile("cp.async.commit_group;" ::: "memory")
#define CPA_WAIT2() asm volatile("cp.async.wait_group 2;" ::: "memory")
#define CPA_WAIT0() asm volatile("cp.async.wait_group 0;" ::: "memory")

#define XBYTES (BM * BK * 2)   // 8192
#define WBYTES (BK * BN * 2)   // 4096

__global__ void __launch_bounds__(256, 3)
hqq_main(const int* __restrict__ tpe, float* __restrict__ Y)
{
    __shared__ __align__(16) uint16_t XS[STAGES][BM * BK];
    __shared__ __align__(16) uint16_t WS[STAGES][BK * BN];

    const int tid = threadIdx.x;
    const int lane = tid & 31;
    const int wid = tid >> 5;
    const int wm = (wid & 3) * 32;
    const int wn = (wid >> 2) * 32;
    const int n0 = blockIdx.x * BN;
    const int m0 = blockIdx.y * BM;

    const uint32_t XtB = (uint32_t)__cvta_generic_to_shared(XS);
    const uint32_t WtB = (uint32_t)__cvta_generic_to_shared(WS);

    uint32_t aoff[2][2], boff[2][2];
#pragma unroll
    for (int mi = 0; mi < 2; ++mi)
#pragma unroll
        for (int s = 0; s < 2; ++s) {
            const int r = wm + mi * 16 + (lane & 15);
            const int c = s * 2 + (lane >> 4);
            aoff[mi][s] = (uint32_t)(r * 64 + ((c ^ ((r >> 1) & 3)) << 4));
        }
#pragma unroll
    for (int s = 0; s < 2; ++s)
#pragma unroll
        for (int nb = 0; nb < 2; ++nb) {
            const int r = s * 16 + (lane & 15);
            const int c = (wn >> 3) + nb * 2 + (lane >> 4);
            boff[s][nb] = (uint32_t)(r * 128 + ((c ^ (r & 7)) << 4));
        }

    // cp.async per-thread maps
    const int xr = tid >> 1;
    const int xc0 = (tid & 1) * 2;
    const uint16_t* xsrc = Xh_buf + (size_t)(m0 + xr) * KDIM + (tid & 1) * 16;
    const uint32_t xd0 = (uint32_t)(xr * 64 + (((xc0 + 0) ^ ((xr >> 1) & 3)) << 4));
    const uint32_t xd1 = (uint32_t)(xr * 64 + (((xc0 + 1) ^ ((xr >> 1) & 3)) << 4));
    const int wr = tid >> 3;
    const int wc = tid & 7;
    const uint32_t wd = (uint32_t)(wr * 128 + ((wc ^ (wr & 7)) << 4));

    int cum = 0;
    for (int e = 0; e < NE; ++e) {
        const int lo = cum;
        cum += tpe[e];
        const int sLo = max(lo, m0), sHi = min(cum, m0 + BM);
        if (sLo >= sHi) continue;

        const uint16_t* wsrc = Wh_buf + (size_t)e * KDIM * ODIM +
                               (size_t)wr * ODIM + n0 + wc * 8;

        // ---- prologue: issue tiles 0..2 ----
#pragma unroll
        for (int p = 0; p < STAGES - 1; ++p) {
            CPA(XtB + p * XBYTES + xd0, xsrc + p * BK);
            CPA(XtB + p * XBYTES + xd1, xsrc + p * BK + 8);
            CPA(WtB + p * WBYTES + wd, wsrc + (size_t)p * BK * ODIM);
            CPA_COMMIT();
        }

        float acc[2][4][4];
#pragma unroll
        for (int i = 0; i < 2; ++i)
#pragma unroll
            for (int j = 0; j < 4; ++j)
#pragma unroll
                for (int r = 0; r < 4; ++r) acc[i][j][r] = 0.f;

#pragma unroll 4
        for (int t = 0; t < NKT; ++t) {
            CPA_WAIT2();
            __syncthreads();

            if (t + STAGES - 1 < NKT) {
                const int sl = (t + STAGES - 1) & (STAGES - 1);
                const int kb = (t + STAGES - 1) * BK;
                CPA(XtB + sl * XBYTES + xd0, xsrc + kb);
                CPA(XtB + sl * XBYTES + xd1, xsrc + kb + 8);
                CPA(WtB + sl * WBYTES + wd, wsrc + (size_t)kb * ODIM);
            }
            CPA_COMMIT();

            const uint32_t XtBb = XtB + (t & (STAGES - 1)) * XBYTES;
            const uint32_t WtBb = WtB + (t & (STAGES - 1)) * WBYTES;

#pragma unroll
            for (int s = 0; s < 2; ++s) {
                uint32_t Av[2][4], Bv[2][4];
                LDSM4(Av[0], XtBb + aoff[0][s]);
                LDSM4(Av[1], XtBb + aoff[1][s]);
                LDSM4T(Bv[0], WtBb + boff[s][0]);
                LDSM4T(Bv[1], WtBb + boff[s][1]);
#pragma unroll
                for (int mi = 0; mi < 2; ++mi)
#pragma unroll
                    for (int nj = 0; nj < 4; ++nj) {
                        const uint32_t b0 = Bv[nj >> 1][(nj & 1) * 2];
                        const uint32_t b1 = Bv[nj >> 1][(nj & 1) * 2 + 1];
                        MMAH(acc[mi][nj], Av[mi], b0, b1);
                    }
            }
        }
        CPA_WAIT0();
        __syncthreads();

        // ---- epilogue: Y += acc on this expert's rows ----
        const int rbase = m0 + wm + (lane >> 2);
        const int cbase = n0 + wn + (lane & 3) * 2;
#pragma unroll
        for (int mi = 0; mi < 2; ++mi)
#pragma unroll
            for (int nj = 0; nj < 4; ++nj) {
                const int r0 = rbase + mi * 16;
                const int c = cbase + nj * 8;
                if (r0 >= sLo && r0 < sHi) {
                    float2* p = (float2*)(Y + (size_t)r0 * ODIM + c);
                    float2 v = *p;
                    v.x += acc[mi][nj][0]; v.y += acc[mi][nj][1];
                    *p = v;
                }
                const int r1 = r0 + 8;
                if (r1 >= sLo && r1 < sHi) {
                    float2* p = (float2*)(Y + (size_t)r1 * ODIM + c);
                    float2 v = *p;
                    v.x += acc[mi][nj][2]; v.y += acc[mi][nj][3];
                    *p = v;
                }
            }
        __syncthreads();
    }
}

extern "C" void kernel_launch(void* const* d_in, const int* in_sizes, int n_in,
                              void* d_out, int out_size) {
    const float* X   = (const float*)d_in[0];
    const int*   tpe = (const int*)d_in[1];
    const int*   Wq  = (const int*)d_in[2];
    const float* Sc  = (const float*)d_in[3];
    const float* Zr  = (const float*)d_in[4];
    float*       Y   = (float*)d_out;

    xcvt_k<<<NTOK, 256>>>(X);
    wcvt_k<<<(NE * KDIM * ODIM) / (256 * 16), 256>>>(Wq, Sc, tpe);
    dim3 gB(ODIM / 128, NTOK / 128);
    yinit_k<<<gB, 256>>>(tpe, Sc, Zr, Y);
    dim3 gM(ODIM / BN, NTOK / BM);                         // 44 x 16
    hqq_main<<<gM, 256>>>(tpe, Y);
}

// round 14
// speedup vs baseline: 1.5318x; 1.2565x over previous
#include <cuda_runtime.h>
#include <cstdint>

// HQQ grouped GEMM: plain fp16 mma.sync pipeline over pre-scaled weights.
// Wh = fp16(s * q); y = x~ . Wh - sum_g s_g*z_g*T[n,g]  (correction fused
// into the main epilogue; T = per-group rowsums of fp16(x)).
// R14: 2 launches total: prep_k (xcvt+wcvt merged), hqq_main (GEMM + corr).
// E=8, K=1024, OUT=2816, GS=64, N=2048.
#define NE 8
#define KDIM 1024
#define ODIM 2816
#define NTOK 2048
#define GD 16           // KDIM/64 quant groups

#define BM 128
#define BN 64
#define BK 32
#define NKT (KDIM / BK) // 32
#define STAGES 4

static __device__ float    T_buf[NTOK * GD];
static __device__ uint16_t Xh_buf[NTOK * KDIM];                       // 4 MB
static __device__ uint16_t Wh_buf[(size_t)NE * KDIM * ODIM];          // 46 MB

__device__ __forceinline__ float h_round(float f) {
    float r;
    asm("{ .reg .f16 t; cvt.rn.f16.f32 t, %1; cvt.f32.f16 %0, t; }"
        : "=f"(r) : "f"(f));
    return r;
}
__device__ __forceinline__ uint32_t cvt2h(float f0, float f1) {
    uint32_t r;
    asm("cvt.rn.f16x2.f32 %0, %1, %2;" : "=r"(r) : "f"(f1), "f"(f0)); // lo = f0
    return r;
}

// ---------------- merged pre-pass: xcvt (blocks 0..2047) + wcvt (rest) ----------------
#define XCVT_BLOCKS NTOK
#define WCVT_BLOCKS ((NE * KDIM * ODIM) / (256 * 8))   // 11264

__global__ void __launch_bounds__(256) prep_k(const float* __restrict__ X,
                                              const int* __restrict__ Wq,
                                              const float* __restrict__ Sc,
                                              const int* __restrict__ tpe) {
    const int t = threadIdx.x;
    if (blockIdx.x < XCVT_BLOCKS) {
        // ---- X -> fp16 scratch + fused group rowsums ----
        const int row = blockIdx.x;
        const float4 v = *(const float4*)(X + (size_t)row * KDIM + t * 4);
        uint32_t h0 = cvt2h(v.x, v.y), h1 = cvt2h(v.z, v.w);
        *(uint2*)(Xh_buf + (size_t)row * KDIM + t * 4) = make_uint2(h0, h1);
        float s = h_round(v.x) + h_round(v.y) + h_round(v.z) + h_round(v.w);
        s += __shfl_xor_sync(0xffffffffu, s, 1);
        s += __shfl_xor_sync(0xffffffffu, s, 2);
        s += __shfl_xor_sync(0xffffffffu, s, 4);
        s += __shfl_xor_sync(0xffffffffu, s, 8);
        if ((t & 15) == 0) T_buf[row * GD + (t >> 4)] = s;
    } else {
        // ---- Wh = fp16(scale * q), 8 elems/thread ----
        const size_t i = ((size_t)(blockIdx.x - XCVT_BLOCKS) * 256 + t) * 8;
        const int e = (int)(i / ((size_t)KDIM * ODIM));
        if (tpe[e] == 0) return;   // expert with no tokens: W never read
        const size_t rem = i % ((size_t)KDIM * ODIM);
        const int k = (int)(rem / ODIM);
        const int o = (int)(rem % ODIM);
        const float* sp = Sc + ((size_t)e * GD + (k >> 6)) * ODIM + o;
        const float4 s0 = *(const float4*)sp;
        const float4 s1 = *(const float4*)(sp + 4);
        const int4 a = *(const int4*)(Wq + i);
        const int4 b = *(const int4*)(Wq + i + 4);
        uint4 oV;
        oV.x = cvt2h(s0.x * (float)a.x, s0.y * (float)a.y);
        oV.y = cvt2h(s0.z * (float)a.z, s0.w * (float)a.w);
        oV.z = cvt2h(s1.x * (float)b.x, s1.y * (float)b.y);
        oV.w = cvt2h(s1.z * (float)b.z, s1.w * (float)b.w);
        *(uint4*)(Wh_buf + i) = oV;
    }
}

// ---------------- main kernel ----------------
#define LDSM4(r, a) asm volatile( \
    "ldmatrix.sync.aligned.m8n8.x4.shared.b16 {%0,%1,%2,%3}, [%4];" \
    : "=r"((r)[0]), "=r"((r)[1]), "=r"((r)[2]), "=r"((r)[3]) : "r"(a))
#define LDSM4T(r, a) asm volatile( \
    "ldmatrix.sync.aligned.m8n8.x4.trans.shared.b16 {%0,%1,%2,%3}, [%4];" \
    : "=r"((r)[0]), "=r"((r)[1]), "=r"((r)[2]), "=r"((r)[3]) : "r"(a))
#define MMAH(d, a, b0, b1) asm volatile( \
    "mma.sync.aligned.m16n8k16.row.col.f32.f16.f16.f32 " \
    "{%0,%1,%2,%3}, {%4,%5,%6,%7}, {%8,%9}, {%0,%1,%2,%3};" \
    : "+f"((d)[0]), "+f"((d)[1]), "+f"((d)[2]), "+f"((d)[3]) \
    : "r"((a)[0]), "r"((a)[1]), "r"((a)[2]), "r"((a)[3]), "r"(b0), "r"(b1))
#define CPA(dst, src) asm volatile( \
    "cp.async.cg.shared.global [%0], [%1], 16;" :: "r"(dst), "l"(src))
#define CPA_COMMIT() asm volatile("cp.async.commit_group;" ::: "memory")
#define CPA_WAIT2() asm volatile("cp.async.wait_group 2;" ::: "memory")
#define CPA_WAIT0() asm volatile("cp.async.wait_group 0;" ::: "memory")

#define XBYTES (BM * BK * 2)   // 8192
#define WBYTES (BK * BN * 2)   // 4096
#define TPITCH 17              // T_s padded pitch (floats)

__global__ void __launch_bounds__(256, 3)
hqq_main(const int* __restrict__ tpe, const float* __restrict__ Sc,
         const float* __restrict__ Zr, float* __restrict__ Y)
{
    __shared__ __align__(16) uint16_t XS[STAGES][BM * BK];
    __shared__ __align__(16) uint16_t WS[STAGES][BK * BN];

    const int tid = threadIdx.x;
    const int lane = tid & 31;
    const int wid = tid >> 5;
    const int wm = (wid & 3) * 32;
    const int wn = (wid >> 2) * 32;
    const int n0 = blockIdx.x * BN;
    const int m0 = blockIdx.y * BM;

    const uint32_t XtB = (uint32_t)__cvta_generic_to_shared(XS);
    const uint32_t WtB = (uint32_t)__cvta_generic_to_shared(WS);

    uint32_t aoff[2][2], boff[2][2];
#pragma unroll
    for (int mi = 0; mi < 2; ++mi)
#pragma unroll
        for (int s = 0; s < 2; ++s) {
            const int r = wm + mi * 16 + (lane & 15);
            const int c = s * 2 + (lane >> 4);
            aoff[mi][s] = (uint32_t)(r * 64 + ((c ^ ((r >> 1) & 3)) << 4));
        }
#pragma unroll
    for (int s = 0; s < 2; ++s)
#pragma unroll
        for (int nb = 0; nb < 2; ++nb) {
            const int r = s * 16 + (lane & 15);
            const int c = (wn >> 3) + nb * 2 + (lane >> 4);
            boff[s][nb] = (uint32_t)(r * 128 + ((c ^ (r & 7)) << 4));
        }

    // cp.async per-thread maps
    const int xr = tid >> 1;
    const int xc0 = (tid & 1) * 2;
    const uint16_t* xsrc = Xh_buf + (size_t)(m0 + xr) * KDIM + (tid & 1) * 16;
    const uint32_t xd0 = (uint32_t)(xr * 64 + (((xc0 + 0) ^ ((xr >> 1) & 3)) << 4));
    const uint32_t xd1 = (uint32_t)(xr * 64 + (((xc0 + 1) ^ ((xr >> 1) & 3)) << 4));
    const int wr = tid >> 3;
    const int wc = tid & 7;
    const uint32_t wd = (uint32_t)(wr * 128 + ((wc ^ (wr & 7)) << 4));

    int cum = 0;
    for (int e = 0; e < NE; ++e) {
        const int lo = cum;
        cum += tpe[e];
        const int sLo = max(lo, m0), sHi = min(cum, m0 + BM);
        if (sLo >= sHi) continue;

        const uint16_t* wsrc = Wh_buf + (size_t)e * KDIM * ODIM +
                               (size_t)wr * ODIM + n0 + wc * 8;

        // ---- prologue: issue tiles 0..2 ----
#pragma unroll
        for (int p = 0; p < STAGES - 1; ++p) {
            CPA(XtB + p * XBYTES + xd0, xsrc + p * BK);
            CPA(XtB + p * XBYTES + xd1, xsrc + p * BK + 8);
            CPA(WtB + p * WBYTES + wd, wsrc + (size_t)p * BK * ODIM);
            CPA_COMMIT();
        }

        float acc[2][4][4];
#pragma unroll
        for (int i = 0; i < 2; ++i)
#pragma unroll
            for (int j = 0; j < 4; ++j)
#pragma unroll
                for (int r = 0; r < 4; ++r) acc[i][j][r] = 0.f;

#pragma unroll 4
        for (int t = 0; t < NKT; ++t) {
            CPA_WAIT2();
            __syncthreads();

            if (t + STAGES - 1 < NKT) {
                const int sl = (t + STAGES - 1) & (STAGES - 1);
                const int kb = (t + STAGES - 1) * BK;
                CPA(XtB + sl * XBYTES + xd0, xsrc + kb);
                CPA(XtB + sl * XBYTES + xd1, xsrc + kb + 8);
                CPA(WtB + sl * WBYTES + wd, wsrc + (size_t)kb * ODIM);
            }
            CPA_COMMIT();

            const uint32_t XtBb = XtB + (t & (STAGES - 1)) * XBYTES;
            const uint32_t WtBb = WtB + (t & (STAGES - 1)) * WBYTES;

#pragma unroll
            for (int s = 0; s < 2; ++s) {
                uint32_t Av[2][4], Bv[2][4];
                LDSM4(Av[0], XtBb + aoff[0][s]);
                LDSM4(Av[1], XtBb + aoff[1][s]);
                LDSM4T(Bv[0], WtBb + boff[s][0]);
                LDSM4T(Bv[1], WtBb + boff[s][1]);
#pragma unroll
                for (int mi = 0; mi < 2; ++mi)
#pragma unroll
                    for (int nj = 0; nj < 4; ++nj) {
                        const uint32_t b0 = Bv[nj >> 1][(nj & 1) * 2];
                        const uint32_t b1 = Bv[nj >> 1][(nj & 1) * 2 + 1];
                        MMAH(acc[mi][nj], Av[mi], b0, b1);
                    }
            }
        }
        CPA_WAIT0();
        __syncthreads();

        // ---- fused zeros-correction: acc -= sum_g (s*z)[g,c] * T[r,g] ----
        // stage u [16 x 64] and T [128 x TPITCH] into the (idle) pipeline smem
        float* u_s = (float*)XS;                          // 4 KB
        float* T_s = (float*)((char*)XS + 4096);          // 128*17*4 = 8.5 KB
        {
            const int g = tid >> 4, c = (tid & 15) * 4;
            const float4 s4 = *(const float4*)(Sc + ((size_t)e * GD + g) * ODIM + n0 + c);
            const float4 z4 = *(const float4*)(Zr + ((size_t)e * GD + g) * ODIM + n0 + c);
            u_s[g * 64 + c + 0] = s4.x * z4.x;
            u_s[g * 64 + c + 1] = s4.y * z4.y;
            u_s[g * 64 + c + 2] = s4.z * z4.z;
            u_s[g * 64 + c + 3] = s4.w * z4.w;
            const int r = tid >> 1, h = (tid & 1) * 8;
            const float4 t0 = *(const float4*)(T_buf + (m0 + r) * GD + h);
            const float4 t1 = *(const float4*)(T_buf + (m0 + r) * GD + h + 4);
            T_s[r * TPITCH + h + 0] = t0.x; T_s[r * TPITCH + h + 1] = t0.y;
            T_s[r * TPITCH + h + 2] = t0.z; T_s[r * TPITCH + h + 3] = t0.w;
            T_s[r * TPITCH + h + 4] = t1.x; T_s[r * TPITCH + h + 5] = t1.y;
            T_s[r * TPITCH + h + 6] = t1.z; T_s[r * TPITCH + h + 7] = t1.w;
        }
        __syncthreads();
        {
            const int rr = wm + (lane >> 2);
            const int cc = wn + (lane & 3) * 2;
#pragma unroll
            for (int g = 0; g < GD; ++g) {
                const float tr0 = T_s[(rr + 0) * TPITCH + g];
                const float tr1 = T_s[(rr + 8) * TPITCH + g];
                const float tr2 = T_s[(rr + 16) * TPITCH + g];
                const float tr3 = T_s[(rr + 24) * TPITCH + g];
#pragma unroll
                for (int nj = 0; nj < 4; ++nj) {
                    const float2 u2 = *(const float2*)&u_s[g * 64 + cc + nj * 8];
                    acc[0][nj][0] -= u2.x * tr0; acc[0][nj][1] -= u2.y * tr0;
                    acc[0][nj][2] -= u2.x * tr1; acc[0][nj][3] -= u2.y * tr1;
                    acc[1][nj][0] -= u2.x * tr2; acc[1][nj][1] -= u2.y * tr2;
                    acc[1][nj][2] -= u2.x * tr3; acc[1][nj][3] -= u2.y * tr3;
                }
            }
        }

        // ---- epilogue: direct store (rows partition across experts) ----
        const int rbase = m0 + wm + (lane >> 2);
        const int cbase = n0 + wn + (lane & 3) * 2;
#pragma unroll
        for (int mi = 0; mi < 2; ++mi)
#pragma unroll
            for (int nj = 0; nj < 4; ++nj) {
                const int r0 = rbase + mi * 16;
                const int c = cbase + nj * 8;
                if (r0 >= sLo && r0 < sHi)
                    *(float2*)(Y + (size_t)r0 * ODIM + c) =
                        make_float2(acc[mi][nj][0], acc[mi][nj][1]);
                const int r1 = r0 + 8;
                if (r1 >= sLo && r1 < sHi)
                    *(float2*)(Y + (size_t)r1 * ODIM + c) =
                        make_float2(acc[mi][nj][2], acc[mi][nj][3]);
            }
        __syncthreads();
    }
}

extern "C" void kernel_launch(void* const* d_in, const int* in_sizes, int n_in,
                              void* d_out, int out_size) {
    const float* X   = (const float*)d_in[0];
    const int*   tpe = (const int*)d_in[1];
    const int*   Wq  = (const int*)d_in[2];
    const float* Sc  = (const float*)d_in[3];
    const float* Zr  = (const float*)d_in[4];
    float*       Y   = (float*)d_out;

    prep_k<<<XCVT_BLOCKS + WCVT_BLOCKS, 256>>>(X, Wq, Sc, tpe);
    dim3 gM(ODIM / BN, NTOK / BM);                         // 44 x 16
    hqq_main<<<gM, 256>>>(tpe, Sc, Zr, Y);
}

// round 15
// speedup vs baseline: 1.6610x; 1.0843x over previous
#include <cuda_runtime.h>
#include <cstdint>

// HQQ grouped GEMM: plain fp16 mma.sync pipeline over pre-scaled weights.
// Wh = fp16(s * q); y = x~ . Wh - sum_g s_g*z_g*T[n,g]  (correction fused
// into the main epilogue; T = per-group rowsums of fp16(x)).
// R15: ragged-waste elimination — warp-level MMA skip outside the expert
// segment + row-level X cp.async predication. Stored values unchanged.
// E=8, K=1024, OUT=2816, GS=64, N=2048.
#define NE 8
#define KDIM 1024
#define ODIM 2816
#define NTOK 2048
#define GD 16           // KDIM/64 quant groups

#define BM 128
#define BN 64
#define BK 32
#define NKT (KDIM / BK) // 32
#define STAGES 4

static __device__ float    T_buf[NTOK * GD];
static __device__ uint16_t Xh_buf[NTOK * KDIM];                       // 4 MB
static __device__ uint16_t Wh_buf[(size_t)NE * KDIM * ODIM];          // 46 MB

__device__ __forceinline__ float h_round(float f) {
    float r;
    asm("{ .reg .f16 t; cvt.rn.f16.f32 t, %1; cvt.f32.f16 %0, t; }"
        : "=f"(r) : "f"(f));
    return r;
}
__device__ __forceinline__ uint32_t cvt2h(float f0, float f1) {
    uint32_t r;
    asm("cvt.rn.f16x2.f32 %0, %1, %2;" : "=r"(r) : "f"(f1), "f"(f0)); // lo = f0
    return r;
}

// ---------------- merged pre-pass: xcvt (blocks 0..2047) + wcvt (rest) ----------------
#define XCVT_BLOCKS NTOK
#define WCVT_BLOCKS ((NE * KDIM * ODIM) / (256 * 8))   // 11264

__global__ void __launch_bounds__(256) prep_k(const float* __restrict__ X,
                                              const int* __restrict__ Wq,
                                              const float* __restrict__ Sc,
                                              const int* __restrict__ tpe) {
    const int t = threadIdx.x;
    if (blockIdx.x < XCVT_BLOCKS) {
        // ---- X -> fp16 scratch + fused group rowsums ----
        const int row = blockIdx.x;
        const float4 v = *(const float4*)(X + (size_t)row * KDIM + t * 4);
        uint32_t h0 = cvt2h(v.x, v.y), h1 = cvt2h(v.z, v.w);
        *(uint2*)(Xh_buf + (size_t)row * KDIM + t * 4) = make_uint2(h0, h1);
        float s = h_round(v.x) + h_round(v.y) + h_round(v.z) + h_round(v.w);
        s += __shfl_xor_sync(0xffffffffu, s, 1);
        s += __shfl_xor_sync(0xffffffffu, s, 2);
        s += __shfl_xor_sync(0xffffffffu, s, 4);
        s += __shfl_xor_sync(0xffffffffu, s, 8);
        if ((t & 15) == 0) T_buf[row * GD + (t >> 4)] = s;
    } else {
        // ---- Wh = fp16(scale * q), 8 elems/thread ----
        const size_t i = ((size_t)(blockIdx.x - XCVT_BLOCKS) * 256 + t) * 8;
        const int e = (int)(i / ((size_t)KDIM * ODIM));
        if (tpe[e] == 0) return;   // expert with no tokens: W never read
        const size_t rem = i % ((size_t)KDIM * ODIM);
        const int k = (int)(rem / ODIM);
        const int o = (int)(rem % ODIM);
        const float* sp = Sc + ((size_t)e * GD + (k >> 6)) * ODIM + o;
        const float4 s0 = *(const float4*)sp;
        const float4 s1 = *(const float4*)(sp + 4);
        const int4 a = *(const int4*)(Wq + i);
        const int4 b = *(const int4*)(Wq + i + 4);
        uint4 oV;
        oV.x = cvt2h(s0.x * (float)a.x, s0.y * (float)a.y);
        oV.y = cvt2h(s0.z * (float)a.z, s0.w * (float)a.w);
        oV.z = cvt2h(s1.x * (float)b.x, s1.y * (float)b.y);
        oV.w = cvt2h(s1.z * (float)b.z, s1.w * (float)b.w);
        *(uint4*)(Wh_buf + i) = oV;
    }
}

// ---------------- main kernel ----------------
#define LDSM4(r, a) asm volatile( \
    "ldmatrix.sync.aligned.m8n8.x4.shared.b16 {%0,%1,%2,%3}, [%4];" \
    : "=r"((r)[0]), "=r"((r)[1]), "=r"((r)[2]), "=r"((r)[3]) : "r"(a))
#define LDSM4T(r, a) asm volatile( \
    "ldmatrix.sync.aligned.m8n8.x4.trans.shared.b16 {%0,%1,%2,%3}, [%4];" \
    : "=r"((r)[0]), "=r"((r)[1]), "=r"((r)[2]), "=r"((r)[3]) : "r"(a))
#define MMAH(d, a, b0, b1) asm volatile( \
    "mma.sync.aligned.m16n8k16.row.col.f32.f16.f16.f32 " \
    "{%0,%1,%2,%3}, {%4,%5,%6,%7}, {%8,%9}, {%0,%1,%2,%3};" \
    : "+f"((d)[0]), "+f"((d)[1]), "+f"((d)[2]), "+f"((d)[3]) \
    : "r"((a)[0]), "r"((a)[1]), "r"((a)[2]), "r"((a)[3]), "r"(b0), "r"(b1))
#define CPA(dst, src) asm volatile( \
    "cp.async.cg.shared.global [%0], [%1], 16;" :: "r"(dst), "l"(src))
#define CPA_COMMIT() asm volatile("cp.async.commit_group;" ::: "memory")
#define CPA_WAIT2() asm volatile("cp.async.wait_group 2;" ::: "memory")
#define CPA_WAIT0() asm volatile("cp.async.wait_group 0;" ::: "memory")

#define XBYTES (BM * BK * 2)   // 8192
#define WBYTES (BK * BN * 2)   // 4096
#define TPITCH 17              // T_s padded pitch (floats)

__global__ void __launch_bounds__(256, 3)
hqq_main(const int* __restrict__ tpe, const float* __restrict__ Sc,
         const float* __restrict__ Zr, float* __restrict__ Y)
{
    __shared__ __align__(16) uint16_t XS[STAGES][BM * BK];
    __shared__ __align__(16) uint16_t WS[STAGES][BK * BN];

    const int tid = threadIdx.x;
    const int lane = tid & 31;
    const int wid = tid >> 5;
    const int wm = (wid & 3) * 32;
    const int wn = (wid >> 2) * 32;
    const int n0 = blockIdx.x * BN;
    const int m0 = blockIdx.y * BM;

    const uint32_t XtB = (uint32_t)__cvta_generic_to_shared(XS);
    const uint32_t WtB = (uint32_t)__cvta_generic_to_shared(WS);

    uint32_t aoff[2][2], boff[2][2];
#pragma unroll
    for (int mi = 0; mi < 2; ++mi)
#pragma unroll
        for (int s = 0; s < 2; ++s) {
            const int r = wm + mi * 16 + (lane & 15);
            const int c = s * 2 + (lane >> 4);
            aoff[mi][s] = (uint32_t)(r * 64 + ((c ^ ((r >> 1) & 3)) << 4));
        }
#pragma unroll
    for (int s = 0; s < 2; ++s)
#pragma unroll
        for (int nb = 0; nb < 2; ++nb) {
            const int r = s * 16 + (lane & 15);
            const int c = (wn >> 3) + nb * 2 + (lane >> 4);
            boff[s][nb] = (uint32_t)(r * 128 + ((c ^ (r & 7)) << 4));
        }

    // cp.async per-thread maps
    const int xr = tid >> 1;               // X row this thread loads (0..127)
    const int xc0 = (tid & 1) * 2;
    const uint16_t* xsrc = Xh_buf + (size_t)(m0 + xr) * KDIM + (tid & 1) * 16;
    const uint32_t xd0 = (uint32_t)(xr * 64 + (((xc0 + 0) ^ ((xr >> 1) & 3)) << 4));
    const uint32_t xd1 = (uint32_t)(xr * 64 + (((xc0 + 1) ^ ((xr >> 1) & 3)) << 4));
    const int wr = tid >> 3;
    const int wc = tid & 7;
    const uint32_t wd = (uint32_t)(wr * 128 + ((wc ^ (wr & 7)) << 4));

    int cum = 0;
    for (int e = 0; e < NE; ++e) {
        const int lo = cum;
        cum += tpe[e];
        const int sLo = max(lo, m0), sHi = min(cum, m0 + BM);
        if (sLo >= sHi) continue;

        const int rlo = sLo - m0, rhi = sHi - m0;        // segment rows in tile
        const bool xact = (xr >= rlo) && (xr < rhi);     // this thread's X row live
        const bool wact = (wm < rhi) && (wm + 32 > rlo); // this warp's band live

        const uint16_t* wsrc = Wh_buf + (size_t)e * KDIM * ODIM +
                               (size_t)wr * ODIM + n0 + wc * 8;

        // ---- prologue: issue tiles 0..2 (X rows predicated to the segment) ----
#pragma unroll
        for (int p = 0; p < STAGES - 1; ++p) {
            if (xact) {
                CPA(XtB + p * XBYTES + xd0, xsrc + p * BK);
                CPA(XtB + p * XBYTES + xd1, xsrc + p * BK + 8);
            }
            CPA(WtB + p * WBYTES + wd, wsrc + (size_t)p * BK * ODIM);
            CPA_COMMIT();
        }

        float acc[2][4][4];
#pragma unroll
        for (int i = 0; i < 2; ++i)
#pragma unroll
            for (int j = 0; j < 4; ++j)
#pragma unroll
                for (int r = 0; r < 4; ++r) acc[i][j][r] = 0.f;

#pragma unroll 4
        for (int t = 0; t < NKT; ++t) {
            CPA_WAIT2();
            __syncthreads();

            if (t + STAGES - 1 < NKT) {
                const int sl = (t + STAGES - 1) & (STAGES - 1);
                const int kb = (t + STAGES - 1) * BK;
                if (xact) {
                    CPA(XtB + sl * XBYTES + xd0, xsrc + kb);
                    CPA(XtB + sl * XBYTES + xd1, xsrc + kb + 8);
                }
                CPA(WtB + sl * WBYTES + wd, wsrc + (size_t)kb * ODIM);
            }
            CPA_COMMIT();

            if (wact) {
                const uint32_t XtBb = XtB + (t & (STAGES - 1)) * XBYTES;
                const uint32_t WtBb = WtB + (t & (STAGES - 1)) * WBYTES;
#pragma unroll
                for (int s = 0; s < 2; ++s) {
                    uint32_t Av[2][4], Bv[2][4];
                    LDSM4(Av[0], XtBb + aoff[0][s]);
                    LDSM4(Av[1], XtBb + aoff[1][s]);
                    LDSM4T(Bv[0], WtBb + boff[s][0]);
                    LDSM4T(Bv[1], WtBb + boff[s][1]);
#pragma unroll
                    for (int mi = 0; mi < 2; ++mi)
#pragma unroll
                        for (int nj = 0; nj < 4; ++nj) {
                            const uint32_t b0 = Bv[nj >> 1][(nj & 1) * 2];
                            const uint32_t b1 = Bv[nj >> 1][(nj & 1) * 2 + 1];
                            MMAH(acc[mi][nj], Av[mi], b0, b1);
                        }
                }
            }
        }
        CPA_WAIT0();
        __syncthreads();

        // ---- fused zeros-correction: acc -= sum_g (s*z)[g,c] * T[r,g] ----
        float* u_s = (float*)XS;                          // 4 KB
        float* T_s = (float*)((char*)XS + 4096);          // 128*17*4 = 8.5 KB
        {
            const int g = tid >> 4, c = (tid & 15) * 4;
            const float4 s4 = *(const float4*)(Sc + ((size_t)e * GD + g) * ODIM + n0 + c);
            const float4 z4 = *(const float4*)(Zr + ((size_t)e * GD + g) * ODIM + n0 + c);
            u_s[g * 64 + c + 0] = s4.x * z4.x;
            u_s[g * 64 + c + 1] = s4.y * z4.y;
            u_s[g * 64 + c + 2] = s4.z * z4.z;
            u_s[g * 64 + c + 3] = s4.w * z4.w;
            const int r = tid >> 1, h = (tid & 1) * 8;
            const float4 t0 = *(const float4*)(T_buf + (m0 + r) * GD + h);
            const float4 t1 = *(const float4*)(T_buf + (m0 + r) * GD + h + 4);
            T_s[r * TPITCH + h + 0] = t0.x; T_s[r * TPITCH + h + 1] = t0.y;
            T_s[r * TPITCH + h + 2] = t0.z; T_s[r * TPITCH + h + 3] = t0.w;
            T_s[r * TPITCH + h + 4] = t1.x; T_s[r * TPITCH + h + 5] = t1.y;
            T_s[r * TPITCH + h + 6] = t1.z; T_s[r * TPITCH + h + 7] = t1.w;
        }
        __syncthreads();
        if (wact) {
            const int rr = wm + (lane >> 2);
            const int cc = wn + (lane & 3) * 2;
#pragma unroll
            for (int g = 0; g < GD; ++g) {
                const float tr0 = T_s[(rr + 0) * TPITCH + g];
                const float tr1 = T_s[(rr + 8) * TPITCH + g];
                const float tr2 = T_s[(rr + 16) * TPITCH + g];
                const float tr3 = T_s[(rr + 24) * TPITCH + g];
#pragma unroll
                for (int nj = 0; nj < 4; ++nj) {
                    const float2 u2 = *(const float2*)&u_s[g * 64 + cc + nj * 8];
                    acc[0][nj][0] -= u2.x * tr0; acc[0][nj][1] -= u2.y * tr0;
                    acc[0][nj][2] -= u2.x * tr1; acc[0][nj][3] -= u2.y * tr1;
                    acc[1][nj][0] -= u2.x * tr2; acc[1][nj][1] -= u2.y * tr2;
                    acc[1][nj][2] -= u2.x * tr3; acc[1][nj][3] -= u2.y * tr3;
                }
            }

            // ---- epilogue: direct store (rows partition across experts) ----
            const int rbase = m0 + wm + (lane >> 2);
            const int cbase = n0 + wn + (lane & 3) * 2;
#pragma unroll
            for (int mi = 0; mi < 2; ++mi)
#pragma unroll
                for (int nj = 0; nj < 4; ++nj) {
                    const int r0 = rbase + mi * 16;
                    const int c = cbase + nj * 8;
                    if (r0 >= sLo && r0 < sHi)
                        *(float2*)(Y + (size_t)r0 * ODIM + c) =
                            make_float2(acc[mi][nj][0], acc[mi][nj][1]);
                    const int r1 = r0 + 8;
                    if (r1 >= sLo && r1 < sHi)
                        *(float2*)(Y + (size_t)r1 * ODIM + c) =
                            make_float2(acc[mi][nj][2], acc[mi][nj][3]);
                }
        }
        __syncthreads();
    }
}

extern "C" void kernel_launch(void* const* d_in, const int* in_sizes, int n_in,
                              void* d_out, int out_size) {
    const float* X   = (const float*)d_in[0];
    const int*   tpe = (const int*)d_in[1];
    const int*   Wq  = (const int*)d_in[2];
    const float* Sc  = (const float*)d_in[3];
    const float* Zr  = (const float*)d_in[4];
    float*       Y   = (float*)d_out;

    prep_k<<<XCVT_BLOCKS + WCVT_BLOCKS, 256>>>(X, Wq, Sc, tpe);
    dim3 gM(ODIM / BN, NTOK / BM);                         // 44 x 16
    hqq_main<<<gM, 256>>>(tpe, Sc, Zr, Y);
}